// round 11
// baseline (speedup 1.0000x reference)
#include <cuda_runtime.h>

#define BATCH 2
#define NSEQ 4096
#define CDIM 128
#define HEADS 4
#define HD 32
#define C2 256
#define MTOT (BATCH*NSEQ)
#define BH (BATCH*HEADS)
#define NROWS (BH*NSEQ)
#define SPLITS 4
#define TILES_PER_SPLIT (NSEQ/32/SPLITS)   // 32
#define KP 40
#define QSCALE (0.17677669529663687f * 1.4426950408889634f)

typedef unsigned long long u64;
typedef unsigned short u16;

// ---------------- scratch ----------------
__device__ float g_o    [MTOT*CDIM];
__device__ float g_xmid [MTOT*CDIM];
__device__ float g_c1   [MTOT*C2];
__device__ float g_gate [MTOT*CDIM];
__device__ float g_pacc [SPLITS*NROWS*HD];
__device__ float g_pl   [SPLITS*NROWS];
__device__ float g_stats1[MTOT*2];   // (mu, rstd) for LN1(x)
__device__ float g_stats2[MTOT*2];   // (mu, rstd) for LN2(g_xmid)
__device__ __align__(16) u16 g_qh[BH*NSEQ*HD];
__device__ __align__(16) u16 g_kh[BH*NSEQ*HD];
__device__ __align__(16) u16 g_vT[BH*NSEQ*HD];

// ---------------- helpers ----------------
__device__ __forceinline__ float ex2(float x) {
    float r; asm("ex2.approx.f32 %0, %1;" : "=f"(r) : "f"(x)); return r;
}
__device__ __forceinline__ unsigned cvt_tf32(float x) {
    unsigned r; asm("cvt.rna.tf32.f32 %0, %1;" : "=r"(r) : "f"(x)); return r;
}
__device__ __forceinline__ float tf32r(float x) { return __uint_as_float(cvt_tf32(x)); }
__device__ __forceinline__ unsigned bf16x2(float hi, float lo) {
    unsigned r;
    asm("cvt.rn.satfinite.bf16x2.f32 %0, %1, %2;" : "=r"(r) : "f"(hi), "f"(lo));
    return r;
}
__device__ __forceinline__ void mma_tf32(float* d,
    unsigned a0, unsigned a1, unsigned a2, unsigned a3, unsigned b0, unsigned b1) {
    asm("mma.sync.aligned.m16n8k8.row.col.f32.tf32.tf32.f32 "
        "{%0,%1,%2,%3}, {%4,%5,%6,%7}, {%8,%9}, {%0,%1,%2,%3};"
        : "+f"(d[0]), "+f"(d[1]), "+f"(d[2]), "+f"(d[3])
        : "r"(a0), "r"(a1), "r"(a2), "r"(a3), "r"(b0), "r"(b1));
}
__device__ __forceinline__ void mma_bf16(float* d,
    unsigned a0, unsigned a1, unsigned a2, unsigned a3, unsigned b0, unsigned b1) {
    asm("mma.sync.aligned.m16n8k16.row.col.f32.bf16.bf16.f32 "
        "{%0,%1,%2,%3}, {%4,%5,%6,%7}, {%8,%9}, {%0,%1,%2,%3};"
        : "+f"(d[0]), "+f"(d[1]), "+f"(d[2]), "+f"(d[3])
        : "r"(a0), "r"(a1), "r"(a2), "r"(a3), "r"(b0), "r"(b1));
}
// ldmatrix x4: four m8n8 b16 matrices; reg j = mat_j[lane/4][2*(lane%4)]
__device__ __forceinline__ void ldsm4(unsigned* r, unsigned addr) {
    asm volatile("ldmatrix.sync.aligned.m8n8.x4.shared.b16 {%0,%1,%2,%3}, [%4];"
        : "=r"(r[0]), "=r"(r[1]), "=r"(r[2]), "=r"(r[3]) : "r"(addr));
}

// ---------------- LN stats: (mu, rstd) per row; 1 warp per row ----------------
template<int WHICH>
__global__ void __launch_bounds__(256) ln_stats(const float* __restrict__ xin, int row0) {
    const float* in = (WHICH == 1) ? xin : g_xmid;
    float*       st = (WHICH == 1) ? g_stats1 : g_stats2;
    const int row = row0 + blockIdx.x*8 + (threadIdx.x >> 5);
    const int lane = threadIdx.x & 31;
    float4 v = *(const float4*)(in + (size_t)row*CDIM + lane*4);
    float s = (v.x + v.y) + (v.z + v.w);
    #pragma unroll
    for (int o = 16; o; o >>= 1) s += __shfl_xor_sync(0xffffffffu, s, o);
    const float mu = s * (1.0f/128.0f);
    float dx = v.x-mu, dy = v.y-mu, dz = v.z-mu, dw = v.w-mu;
    float q = (dx*dx + dy*dy) + (dz*dz + dw*dw);
    #pragma unroll
    for (int o = 16; o; o >>= 1) q += __shfl_xor_sync(0xffffffffu, q, o);
    if (lane == 0)
        *(float2*)&st[row*2] = make_float2(mu, rsqrtf(q*(1.0f/128.0f) + 1e-5f));
}

// ---------------- GEMM: out[m,o] = sum_k LN?(A[m,k]) W[o,k], K=128 ----------------
template<int MODE>
__global__ void __launch_bounds__(128) gemm_mma(const float* __restrict__ Aext,
                                                const float* __restrict__ W0,
                                                const float* __restrict__ W1,
                                                const float* __restrict__ bias,
                                                const float* __restrict__ lnw,
                                                const float* __restrict__ lnb,
                                                const float* __restrict__ resid_ext,
                                                float* __restrict__ out_ext) {
    constexpr bool EX = (MODE != 0);
    constexpr bool LN = (MODE == 0 || MODE == 2);
    const float* A;
    if (MODE == 0)      A = Aext;
    else if (MODE == 1) A = g_o;
    else if (MODE == 2) A = g_xmid;
    else                A = g_gate;
    const float* stats = (MODE == 0) ? g_stats1 : g_stats2;

    __shared__ float Ah[64][20], Wh[64][20];
    __shared__ float Al[EX ? 64 : 1][20], Wl[EX ? 64 : 1][20];

    const int t = threadIdx.x;
    const int warp = t >> 5, lane = t & 31;
    const int g = lane >> 2, tg = lane & 3;
    const int m0 = blockIdx.x * 64;
    const int o0 = blockIdx.y * 64;
    const int lrow = t >> 2, c4 = (t & 3) * 4;

    float s[8][4] = {};

    float2 st0, st1;
    if (LN) {
        st0 = *(const float2*)(stats + (size_t)(m0 + lrow)*2);
        st1 = *(const float2*)(stats + (size_t)(m0 + lrow + 32)*2);
    }

    float4 a0, a1, w0v, w1v, lw, lb;

#define GEMM_LOAD(kc_) {                                                        \
        const int k0_ = (kc_)*16;                                               \
        a0 = *(const float4*)(A + (size_t)(m0 + lrow     )*CDIM + k0_ + c4);    \
        a1 = *(const float4*)(A + (size_t)(m0 + lrow + 32)*CDIM + k0_ + c4);    \
        { int o_ = o0 + lrow;                                                   \
          const float* wr_;                                                     \
          if (MODE == 0) wr_ = (o_ < CDIM) ? (W0 + (size_t)o_*CDIM)             \
                                           : (W1 + (size_t)(o_ - CDIM)*CDIM);   \
          else           wr_ = W0 + (size_t)o_*CDIM;                            \
          w0v = *(const float4*)(wr_ + k0_ + c4); }                             \
        { int o_ = o0 + lrow + 32;                                              \
          const float* wr_;                                                     \
          if (MODE == 0) wr_ = (o_ < CDIM) ? (W0 + (size_t)o_*CDIM)             \
                                           : (W1 + (size_t)(o_ - CDIM)*CDIM);   \
          else           wr_ = W0 + (size_t)o_*CDIM;                            \
          w1v = *(const float4*)(wr_ + k0_ + c4); }                             \
        if (LN) { lw = *(const float4*)(lnw + k0_ + c4);                        \
                  lb = *(const float4*)(lnb + k0_ + c4); } }

    GEMM_LOAD(0);

    #pragma unroll
    for (int kc = 0; kc < 8; ++kc) {
        if (kc) __syncthreads();
        if (LN) {
            a0.x = (a0.x - st0.x)*st0.y*lw.x + lb.x;
            a0.y = (a0.y - st0.x)*st0.y*lw.y + lb.y;
            a0.z = (a0.z - st0.x)*st0.y*lw.z + lb.z;
            a0.w = (a0.w - st0.x)*st0.y*lw.w + lb.w;
            a1.x = (a1.x - st1.x)*st1.y*lw.x + lb.x;
            a1.y = (a1.y - st1.x)*st1.y*lw.y + lb.y;
            a1.z = (a1.z - st1.x)*st1.y*lw.z + lb.z;
            a1.w = (a1.w - st1.x)*st1.y*lw.w + lb.w;
        }
        {
            float4 h0, h1;
            h0.x = tf32r(a0.x); h0.y = tf32r(a0.y); h0.z = tf32r(a0.z); h0.w = tf32r(a0.w);
            h1.x = tf32r(a1.x); h1.y = tf32r(a1.y); h1.z = tf32r(a1.z); h1.w = tf32r(a1.w);
            *(float4*)&Ah[lrow     ][c4] = h0;
            *(float4*)&Ah[lrow + 32][c4] = h1;
            if (EX) {
                float4 l0, l1;
                l0.x = tf32r(a0.x - h0.x); l0.y = tf32r(a0.y - h0.y);
                l0.z = tf32r(a0.z - h0.z); l0.w = tf32r(a0.w - h0.w);
                l1.x = tf32r(a1.x - h1.x); l1.y = tf32r(a1.y - h1.y);
                l1.z = tf32r(a1.z - h1.z); l1.w = tf32r(a1.w - h1.w);
                *(float4*)&Al[lrow     ][c4] = l0;
                *(float4*)&Al[lrow + 32][c4] = l1;
            }
            float4 hw0, hw1;
            hw0.x = tf32r(w0v.x); hw0.y = tf32r(w0v.y); hw0.z = tf32r(w0v.z); hw0.w = tf32r(w0v.w);
            hw1.x = tf32r(w1v.x); hw1.y = tf32r(w1v.y); hw1.z = tf32r(w1v.z); hw1.w = tf32r(w1v.w);
            *(float4*)&Wh[lrow     ][c4] = hw0;
            *(float4*)&Wh[lrow + 32][c4] = hw1;
            if (EX) {
                float4 l0, l1;
                l0.x = tf32r(w0v.x - hw0.x); l0.y = tf32r(w0v.y - hw0.y);
                l0.z = tf32r(w0v.z - hw0.z); l0.w = tf32r(w0v.w - hw0.w);
                l1.x = tf32r(w1v.x - hw1.x); l1.y = tf32r(w1v.y - hw1.y);
                l1.z = tf32r(w1v.z - hw1.z); l1.w = tf32r(w1v.w - hw1.w);
                *(float4*)&Wl[lrow     ][c4] = l0;
                *(float4*)&Wl[lrow + 32][c4] = l1;
            }
        }
        __syncthreads();
        if (kc < 7) GEMM_LOAD(kc + 1);

        #pragma unroll
        for (int ks = 0; ks < 2; ++ks) {
            const int k = ks * 8;
            const int mr = 16*warp;
            unsigned ah[4], al[4];
            ah[0] = __float_as_uint(Ah[mr + g    ][k + tg    ]);
            ah[1] = __float_as_uint(Ah[mr + g + 8][k + tg    ]);
            ah[2] = __float_as_uint(Ah[mr + g    ][k + tg + 4]);
            ah[3] = __float_as_uint(Ah[mr + g + 8][k + tg + 4]);
            if (EX) {
                al[0] = __float_as_uint(Al[mr + g    ][k + tg    ]);
                al[1] = __float_as_uint(Al[mr + g + 8][k + tg    ]);
                al[2] = __float_as_uint(Al[mr + g    ][k + tg + 4]);
                al[3] = __float_as_uint(Al[mr + g + 8][k + tg + 4]);
            }
            #pragma unroll
            for (int nt = 0; nt < 8; ++nt) {
                unsigned bh0 = __float_as_uint(Wh[8*nt + g][k + tg    ]);
                unsigned bh1 = __float_as_uint(Wh[8*nt + g][k + tg + 4]);
                mma_tf32(s[nt], ah[0], ah[1], ah[2], ah[3], bh0, bh1);
                if (EX) {
                    unsigned bl0 = __float_as_uint(Wl[8*nt + g][k + tg    ]);
                    unsigned bl1 = __float_as_uint(Wl[8*nt + g][k + tg + 4]);
                    mma_tf32(s[nt], ah[0], ah[1], ah[2], ah[3], bl0, bl1);
                    mma_tf32(s[nt], al[0], al[1], al[2], al[3], bh0, bh1);
                }
            }
        }
    }
#undef GEMM_LOAD

    // ---- epilogue ----
    const int mA = m0 + 16*warp + g;
    #pragma unroll
    for (int nt = 0; nt < 8; ++nt) {
        const int o = o0 + 8*nt + 2*tg;
        float2 v01 = make_float2(s[nt][0], s[nt][1]);
        float2 v23 = make_float2(s[nt][2], s[nt][3]);
        if (MODE == 0) {
            #pragma unroll
            for (int hf = 0; hf < 2; ++hf) {
                const int m = mA + 8*hf;
                float2 v = hf ? v23 : v01;
                const int b = m >> 12, n = m & 4095;
                if (o < 128) {
                    const int head = o >> 5, hd = o & 31;
                    *(unsigned*)&g_qh[((size_t)(b*HEADS + head)*NSEQ + n)*HD + hd] =
                        bf16x2(v.y*QSCALE, v.x*QSCALE);
                } else if (o < 256) {
                    const int oo = o - 128, head = oo >> 5, hd = oo & 31;
                    *(unsigned*)&g_kh[((size_t)(b*HEADS + head)*NSEQ + n)*HD + hd] =
                        bf16x2(v.y, v.x);
                } else {
                    const int oo = o - 256, head = oo >> 5, hd = oo & 31;
                    unsigned u = bf16x2(v.y, v.x);
                    size_t base = ((size_t)((b*HEADS + head)*128 + (n >> 5))*32 + hd)*32 + (n & 31);
                    g_vT[base]      = (u16)(u & 0xffffu);
                    g_vT[base + 32] = (u16)(u >> 16);
                }
            }
        } else if (MODE == 2) {
            float2 bv = *(const float2*)(bias + o);
            *(float2*)&g_c1[(size_t)mA*C2 + o] =
                make_float2(v01.x + bv.x, v01.y + bv.y);
            *(float2*)&g_c1[(size_t)(mA+8)*C2 + o] =
                make_float2(v23.x + bv.x, v23.y + bv.y);
        } else {
            const float* rs = (MODE == 1) ? resid_ext : g_xmid;
            float*       ds = (MODE == 1) ? g_xmid    : out_ext;
            float2 bv = *(const float2*)(bias + o);
            float2 r0 = *(const float2*)(rs + (size_t)mA*CDIM + o);
            float2 r1 = *(const float2*)(rs + (size_t)(mA+8)*CDIM + o);
            *(float2*)&ds[(size_t)mA*CDIM + o] =
                make_float2(v01.x + bv.x + r0.x, v01.y + bv.y + r0.y);
            *(float2*)&ds[(size_t)(mA+8)*CDIM + o] =
                make_float2(v23.x + bv.x + r1.x, v23.y + bv.y + r1.y);
        }
    }
}

// ---------------- Flash attention: bf16 m16n8k16, split-KV, ldmatrix frags ----------------
__global__ void __launch_bounds__(128, 4) attn_kernel() {
    const int bh    = blockIdx.x;
    const int split = blockIdx.z;
    const int t     = threadIdx.x;
    const int warp  = t >> 5;
    const int lane  = t & 31;
    const int g     = lane >> 2;
    const int tg    = lane & 3;

    const int q0 = blockIdx.y*128 + warp*32;
    const u16* Qb  = g_qh + ((size_t)bh*NSEQ + q0)*HD;
    const u16* Kb  = g_kh + ((size_t)bh*NSEQ + (size_t)split*(NSEQ/SPLITS))*HD;
    const u16* Vtb = g_vT + ((size_t)(bh*128 + split*32))*1024;

    unsigned qf[2][2][4];
    #pragma unroll
    for (int mt = 0; mt < 2; ++mt)
        #pragma unroll
        for (int kk = 0; kk < 2; ++kk) {
            qf[mt][kk][0] = *(const unsigned*)&Qb[(16*mt + g    )*HD + 16*kk + 2*tg    ];
            qf[mt][kk][1] = *(const unsigned*)&Qb[(16*mt + g + 8)*HD + 16*kk + 2*tg    ];
            qf[mt][kk][2] = *(const unsigned*)&Qb[(16*mt + g    )*HD + 16*kk + 2*tg + 8];
            qf[mt][kk][3] = *(const unsigned*)&Qb[(16*mt + g + 8)*HD + 16*kk + 2*tg + 8];
        }

    __shared__ u16 Ks[2][32][KP];
    __shared__ u16 Vt[2][32][KP];

    // ldmatrix per-lane row address: lane L -> row (L&7), col block 8*(L>>3)
    const unsigned ksBase = (unsigned)__cvta_generic_to_shared(&Ks[0][0][0])
                          + (unsigned)(((lane & 7)*KP + (lane >> 3)*8) * 2);
    const unsigned vtBase = (unsigned)__cvta_generic_to_shared(&Vt[0][0][0])
                          + (unsigned)(((lane & 7)*KP + (lane >> 3)*8) * 2);
    const unsigned BUFSZ = 32*KP*2;   // bytes per buffer
    const unsigned NTSZ  = 8*KP*2;    // bytes per 8-row group

    float o[2][4][4] = {};
    float l[4] = {};

    const int lr  = t >> 2;
    const int lc8 = (t & 3) * 8;
    const float4* kptr = (const float4*)Kb  + t;
    const float4* vptr = (const float4*)Vtb + t;

    float4 ka = kptr[0];
    float4 va = vptr[0];

    for (int kt = 0; kt < TILES_PER_SPLIT; ++kt) {
        const int buf = kt & 1;
        const unsigned bufOff = buf * BUFSZ;
        *(float4*)&Ks[buf][lr][lc8] = ka;
        *(float4*)&Vt[buf][lr][lc8] = va;
        __syncthreads();

        if (kt + 1 < TILES_PER_SPLIT) {
            ka = kptr[(kt+1)*128];
            va = vptr[(kt+1)*128];
        }

        // ---- S = Q K^T (log2 domain); one LDSM.x4 per n-tile ----
        float s[2][4][4] = {};
        #pragma unroll
        for (int nt = 0; nt < 4; ++nt) {
            unsigned kb[4];
            ldsm4(kb, ksBase + bufOff + nt*NTSZ);
            mma_bf16(s[0][nt], qf[0][0][0], qf[0][0][1], qf[0][0][2], qf[0][0][3], kb[0], kb[1]);
            mma_bf16(s[0][nt], qf[0][1][0], qf[0][1][1], qf[0][1][2], qf[0][1][3], kb[2], kb[3]);
            mma_bf16(s[1][nt], qf[1][0][0], qf[1][0][1], qf[1][0][2], qf[1][0][3], kb[0], kb[1]);
            mma_bf16(s[1][nt], qf[1][1][0], qf[1][1][1], qf[1][1][2], qf[1][1][3], kb[2], kb[3]);
        }

        // ---- softmax (ex2) + pack P to bf16x2 ----
        unsigned pk[2][4][2];
        #pragma unroll
        for (int nt = 0; nt < 4; ++nt)
            #pragma unroll
            for (int mt = 0; mt < 2; ++mt) {
                float e0 = ex2(s[mt][nt][0]);
                float e1 = ex2(s[mt][nt][1]);
                float e2 = ex2(s[mt][nt][2]);
                float e3 = ex2(s[mt][nt][3]);
                l[2*mt]   += e0 + e1;
                l[2*mt+1] += e2 + e3;
                pk[mt][nt][0] = bf16x2(e1, e0);
                pk[mt][nt][1] = bf16x2(e3, e2);
            }

        // ---- O += P V; one LDSM.x4 per d-tile ----
        #pragma unroll
        for (int nd = 0; nd < 4; ++nd) {
            unsigned vb[4];
            ldsm4(vb, vtBase + bufOff + nd*NTSZ);
            #pragma unroll
            for (int mt = 0; mt < 2; ++mt) {
                mma_bf16(o[mt][nd], pk[mt][0][0], pk[mt][0][1],
                                    pk[mt][1][0], pk[mt][1][1], vb[0], vb[1]);
                mma_bf16(o[mt][nd], pk[mt][2][0], pk[mt][2][1],
                                    pk[mt][3][0], pk[mt][3][1], vb[2], vb[3]);
            }
        }
    }

    #pragma unroll
    for (int i = 0; i < 4; ++i) {
        l[i] += __shfl_xor_sync(0xffffffffu, l[i], 1);
        l[i] += __shfl_xor_sync(0xffffffffu, l[i], 2);
    }

    #pragma unroll
    for (int mt = 0; mt < 2; ++mt) {
        const size_t row = (size_t)bh*NSEQ + q0 + 16*mt + g;
        float* base0 = g_pacc + ((size_t)split*NROWS + row)*HD;
        float* base1 = base0 + 8*HD;
        #pragma unroll
        for (int nd = 0; nd < 4; ++nd) {
            *(float2*)(base0 + 8*nd + 2*tg) = make_float2(o[mt][nd][0], o[mt][nd][1]);
            *(float2*)(base1 + 8*nd + 2*tg) = make_float2(o[mt][nd][2], o[mt][nd][3]);
        }
        if (tg == 0) {
            g_pl[(size_t)split*NROWS + row    ] = l[2*mt];
            g_pl[(size_t)split*NROWS + row + 8] = l[2*mt+1];
        }
    }
}

// ---------------- combine split-KV partials -> g_o ----------------
__global__ void __launch_bounds__(256) attn_reduce() {
    const int idx = blockIdx.x * 256 + threadIdx.x;
    const int row = idx >> 3;
    const int d4  = idx & 7;

    float4 a = make_float4(0.f, 0.f, 0.f, 0.f);
    float l = 0.0f;
    #pragma unroll
    for (int s = 0; s < SPLITS; ++s) {
        const float* pa = g_pacc + ((size_t)s*NROWS + row)*HD + d4*4;
        float4 v = *(const float4*)pa;
        a.x += v.x; a.y += v.y; a.z += v.z; a.w += v.w;
        l += g_pl[(size_t)s*NROWS + row];
    }
    const float inv = 1.0f / l;
    const int bh = row >> 12, n = row & 4095;
    const int b = bh >> 2, h = bh & 3;
    float* O = g_o + ((size_t)(b*NSEQ + n))*CDIM + h*HD + d4*4;
    *(float4*)O = make_float4(a.x*inv, a.y*inv, a.z*inv, a.w*inv);
}

// ---------------- fused DW 3x3 + DW 5x5 + sum + SimpleGate (8 px/block) ----------------
__global__ void __launch_bounds__(1024) dw_gate_kernel(const float* __restrict__ w33,
                                                       const float* __restrict__ b33,
                                                       const float* __restrict__ w55,
                                                       const float* __restrict__ b55) {
    __shared__ float s33[C2*9];
    __shared__ float s55[C2*25];
    __shared__ float sb[C2];

    const int tid = threadIdx.y*128 + threadIdx.x;
    for (int i = tid; i < C2*9;  i += 1024) s33[i] = w33[i];
    for (int i = tid; i < C2*25; i += 1024) s55[i] = w55[i];
    if (tid < C2) sb[tid] = b33[tid] + b55[tid];
    __syncthreads();

    const int p = blockIdx.x * 8 + threadIdx.y;
    const int b = p >> 12;
    const int n = p & 4095;
    const int y = n >> 6, x = n & 63;
    const int ca = threadIdx.x;
    const int cg = ca + 128;
    const float* base = g_c1 + (size_t)b*NSEQ*C2;

    float acc_a = sb[ca] + base[(size_t)n*C2 + ca];
    float acc_g = sb[cg] + base[(size_t)n*C2 + cg];

    #pragma unroll
    for (int dy = -2; dy <= 2; ++dy) {
        const int yy = y + dy;
        if (yy < 0 || yy > 63) continue;
        #pragma unroll
        for (int dx = -2; dx <= 2; ++dx) {
            const int xx = x + dx;
            if (xx < 0 || xx > 63) continue;
            const float* px = base + (size_t)(yy*64 + xx)*C2;
            const float va = px[ca];
            const float vg = px[cg];
            const int i5 = (dy+2)*5 + (dx+2);
            acc_a = fmaf(va, s55[ca*25 + i5], acc_a);
            acc_g = fmaf(vg, s55[cg*25 + i5], acc_g);
            if (dy >= -1 && dy <= 1 && dx >= -1 && dx <= 1) {
                const int i3 = (dy+1)*3 + (dx+1);
                acc_a = fmaf(va, s33[ca*9 + i3], acc_a);
                acc_g = fmaf(vg, s33[cg*9 + i3], acc_g);
            }
        }
    }
    g_gate[(size_t)(b*NSEQ + n)*CDIM + ca] = acc_a * acc_g;
}

// ---------------- launch ----------------
extern "C" void kernel_launch(void* const* d_in, const int* in_sizes, int n_in,
                              void* d_out, int out_size) {
    (void)in_sizes; (void)n_in; (void)out_size;
    const float* x       = (const float*)d_in[0];
    const float* ln1_w   = (const float*)d_in[3];
    const float* ln1_b   = (const float*)d_in[4];
    const float* q_w     = (const float*)d_in[5];
    const float* kv_w    = (const float*)d_in[6];
    const float* proj_w  = (const float*)d_in[7];
    const float* proj_b  = (const float*)d_in[8];
    const float* ln2_w   = (const float*)d_in[9];
    const float* ln2_b   = (const float*)d_in[10];
    const float* conv1_w = (const float*)d_in[11];
    const float* conv1_b = (const float*)d_in[12];
    const float* conv33_w= (const float*)d_in[13];
    const float* conv33_b= (const float*)d_in[14];
    const float* conv55_w= (const float*)d_in[15];
    const float* conv55_b= (const float*)d_in[16];
    const float* conv4_w = (const float*)d_in[17];
    const float* conv4_b = (const float*)d_in[18];
    float* out = (float*)d_out;

    ln_stats<1><<<MTOT/16, 256>>>(x, 0);                                         // 0
    ln_stats<1><<<MTOT/16, 256>>>(x, MTOT/2);                                    // 1
    gemm_mma<0><<<dim3(128, 6), 128>>>(x, q_w, kv_w, nullptr,
                                       ln1_w, ln1_b, nullptr, nullptr);          // 2
    attn_kernel<<<dim3(8, 32, 4), 128>>>();                                      // 3 (profiled)
    attn_reduce<<<NROWS*8/256, 256>>>();                                         // 4
    gemm_mma<1><<<dim3(128, 2), 128>>>(nullptr, proj_w, nullptr, proj_b,
                                       nullptr, nullptr, x, nullptr);            // 5
    ln_stats<2><<<MTOT/8, 256>>>(nullptr, 0);                                    // 6
    gemm_mma<2><<<dim3(128, 4), 128>>>(nullptr, conv1_w, nullptr, conv1_b,
                                       ln2_w, ln2_b, nullptr, nullptr);          // 7
    dw_gate_kernel<<<1024, dim3(128, 8)>>>(conv33_w, conv33_b, conv55_w, conv55_b); // 8
    gemm_mma<3><<<dim3(128, 2), 128>>>(nullptr, conv4_w, nullptr, conv4_b,
                                       nullptr, nullptr, nullptr, out);          // 9
}

// round 12
// speedup vs baseline: 1.1276x; 1.1276x over previous
#include <cuda_runtime.h>

#define BATCH 2
#define NSEQ 4096
#define CDIM 128
#define HEADS 4
#define HD 32
#define C2 256
#define MTOT (BATCH*NSEQ)
#define BH (BATCH*HEADS)
#define NROWS (BH*NSEQ)
#define SPLITS 4
#define TILES_PER_SPLIT (NSEQ/32/SPLITS)   // 32
#define KP 40
#define QSCALE (0.17677669529663687f * 1.4426950408889634f)

typedef unsigned long long u64;
typedef unsigned short u16;

// ---------------- scratch ----------------
__device__ float g_xmid [MTOT*CDIM];
__device__ float g_c1   [MTOT*C2];
__device__ float g_gate [MTOT*CDIM];
__device__ float g_pacc [SPLITS*NROWS*HD];
__device__ float g_pl   [SPLITS*NROWS];
__device__ float g_stats1[MTOT*2];
__device__ float g_stats2[MTOT*2];
__device__ __align__(16) u16 g_qh[BH*NSEQ*HD];
__device__ __align__(16) u16 g_kh[BH*NSEQ*HD];
__device__ __align__(16) u16 g_vT[BH*NSEQ*HD];

// ---------------- helpers ----------------
__device__ __forceinline__ float ex2(float x) {
    float r; asm("ex2.approx.f32 %0, %1;" : "=f"(r) : "f"(x)); return r;
}
__device__ __forceinline__ unsigned cvt_tf32(float x) {
    unsigned r; asm("cvt.rna.tf32.f32 %0, %1;" : "=r"(r) : "f"(x)); return r;
}
__device__ __forceinline__ float tf32r(float x) { return __uint_as_float(cvt_tf32(x)); }
__device__ __forceinline__ unsigned bf16x2(float hi, float lo) {
    unsigned r;
    asm("cvt.rn.satfinite.bf16x2.f32 %0, %1, %2;" : "=r"(r) : "f"(hi), "f"(lo));
    return r;
}
__device__ __forceinline__ void mma_tf32(float* d,
    unsigned a0, unsigned a1, unsigned a2, unsigned a3, unsigned b0, unsigned b1) {
    asm("mma.sync.aligned.m16n8k8.row.col.f32.tf32.tf32.f32 "
        "{%0,%1,%2,%3}, {%4,%5,%6,%7}, {%8,%9}, {%0,%1,%2,%3};"
        : "+f"(d[0]), "+f"(d[1]), "+f"(d[2]), "+f"(d[3])
        : "r"(a0), "r"(a1), "r"(a2), "r"(a3), "r"(b0), "r"(b1));
}
__device__ __forceinline__ void mma_bf16(float* d,
    unsigned a0, unsigned a1, unsigned a2, unsigned a3, unsigned b0, unsigned b1) {
    asm("mma.sync.aligned.m16n8k16.row.col.f32.bf16.bf16.f32 "
        "{%0,%1,%2,%3}, {%4,%5,%6,%7}, {%8,%9}, {%0,%1,%2,%3};"
        : "+f"(d[0]), "+f"(d[1]), "+f"(d[2]), "+f"(d[3])
        : "r"(a0), "r"(a1), "r"(a2), "r"(a3), "r"(b0), "r"(b1));
}

// ---------------- LN stats: (mu, rstd) per row; 1 warp per row ----------------
template<int WHICH>
__global__ void __launch_bounds__(256) ln_stats(const float* __restrict__ xin) {
    const float* in = (WHICH == 1) ? xin : g_xmid;
    float*       st = (WHICH == 1) ? g_stats1 : g_stats2;
    const int row = blockIdx.x*8 + (threadIdx.x >> 5);
    const int lane = threadIdx.x & 31;
    float4 v = *(const float4*)(in + (size_t)row*CDIM + lane*4);
    float s = (v.x + v.y) + (v.z + v.w);
    #pragma unroll
    for (int o = 16; o; o >>= 1) s += __shfl_xor_sync(0xffffffffu, s, o);
    const float mu = s * (1.0f/128.0f);
    float dx = v.x-mu, dy = v.y-mu, dz = v.z-mu, dw = v.w-mu;
    float q = (dx*dx + dy*dy) + (dz*dz + dw*dw);
    #pragma unroll
    for (int o = 16; o; o >>= 1) q += __shfl_xor_sync(0xffffffffu, q, o);
    if (lane == 0)
        *(float2*)&st[row*2] = make_float2(mu, rsqrtf(q*(1.0f/128.0f) + 1e-5f));
}

// ---------------- GEMM: out[m,o] = sum_k LN?(A[m,k]) W[o,k], K=128 ----------------
// MODE 0: A=x(arg)+LN1, single tf32, bf16 out (Q scale folded)
// MODE 1: A = split-KV reduce of g_pacc/g_pl (fused), 3xTF32, +bias +resid(x) -> g_xmid
// MODE 2: A=g_xmid+LN2, 3xTF32, +bias -> g_c1
// MODE 3: A=g_gate,     3xTF32, +bias +resid(g_xmid) -> out_ext
template<int MODE>
__global__ void __launch_bounds__(128) gemm_mma(const float* __restrict__ Aext,
                                                const float* __restrict__ W0,
                                                const float* __restrict__ W1,
                                                const float* __restrict__ bias,
                                                const float* __restrict__ lnw,
                                                const float* __restrict__ lnb,
                                                const float* __restrict__ resid_ext,
                                                float* __restrict__ out_ext) {
    constexpr bool EX = (MODE != 0);
    constexpr bool LN = (MODE == 0 || MODE == 2);
    const float* A;
    if (MODE == 0)      A = Aext;
    else if (MODE == 1) A = nullptr;      // fused pacc reduce
    else if (MODE == 2) A = g_xmid;
    else                A = g_gate;
    const float* stats = (MODE == 0) ? g_stats1 : g_stats2;

    __shared__ float Ah[64][20], Wh[64][20];
    __shared__ float Al[EX ? 64 : 1][20], Wl[EX ? 64 : 1][20];

    const int t = threadIdx.x;
    const int warp = t >> 5, lane = t & 31;
    const int g = lane >> 2, tg = lane & 3;
    const int m0 = blockIdx.x * 64;
    const int o0 = blockIdx.y * 64;
    const int lrow = t >> 2, c4 = (t & 3) * 4;

    float s[8][4] = {};

    float2 st0, st1;
    if (LN) {
        st0 = *(const float2*)(stats + (size_t)(m0 + lrow)*2);
        st1 = *(const float2*)(stats + (size_t)(m0 + lrow + 32)*2);
    }

    // MODE 1: precompute per-row, per-head 1/l
    int b0_ = 0, n0_ = 0, b1_ = 0, n1_ = 0;
    float invl0[4], invl1[4];
    float4 p0[4], p1[4];
    if (MODE == 1) {
        int m_ = m0 + lrow;  b0_ = m_ >> 12;  n0_ = m_ & 4095;
        int m2_ = m_ + 32;   b1_ = m2_ >> 12; n1_ = m2_ & 4095;
        #pragma unroll
        for (int h = 0; h < 4; ++h) {
            size_t r0 = (size_t)((b0_*4 + h)*4096 + n0_);
            size_t r1 = (size_t)((b1_*4 + h)*4096 + n1_);
            float l0 = g_pl[r0] + g_pl[(size_t)NROWS + r0]
                     + g_pl[2*(size_t)NROWS + r0] + g_pl[3*(size_t)NROWS + r0];
            float l1 = g_pl[r1] + g_pl[(size_t)NROWS + r1]
                     + g_pl[2*(size_t)NROWS + r1] + g_pl[3*(size_t)NROWS + r1];
            invl0[h] = 1.0f / l0;
            invl1[h] = 1.0f / l1;
        }
    }

    float4 a0, a1, w0v, w1v, lw, lb;

#define GEMM_LOAD(kc_) {                                                        \
        const int k0_ = (kc_)*16;                                               \
        if (MODE == 1) {                                                        \
            const int h_ = k0_ >> 5;                                            \
            const int hb_ = (k0_ & 31) + c4;                                    \
            const size_t r0_ = (size_t)((b0_*4 + h_)*4096 + n0_);               \
            const size_t r1_ = (size_t)((b1_*4 + h_)*4096 + n1_);               \
            _Pragma("unroll")                                                   \
            for (int s_ = 0; s_ < 4; ++s_) {                                    \
                p0[s_] = *(const float4*)(g_pacc + (((size_t)s_*NROWS + r0_)<<5) + hb_); \
                p1[s_] = *(const float4*)(g_pacc + (((size_t)s_*NROWS + r1_)<<5) + hb_); \
            }                                                                   \
        } else {                                                                \
            a0 = *(const float4*)(A + (size_t)(m0 + lrow     )*CDIM + k0_ + c4);\
            a1 = *(const float4*)(A + (size_t)(m0 + lrow + 32)*CDIM + k0_ + c4);\
        }                                                                       \
        { int o_ = o0 + lrow;                                                   \
          const float* wr_;                                                     \
          if (MODE == 0) wr_ = (o_ < CDIM) ? (W0 + (size_t)o_*CDIM)             \
                                           : (W1 + (size_t)(o_ - CDIM)*CDIM);   \
          else           wr_ = W0 + (size_t)o_*CDIM;                            \
          w0v = *(const float4*)(wr_ + k0_ + c4); }                             \
        { int o_ = o0 + lrow + 32;                                              \
          const float* wr_;                                                     \
          if (MODE == 0) wr_ = (o_ < CDIM) ? (W0 + (size_t)o_*CDIM)             \
                                           : (W1 + (size_t)(o_ - CDIM)*CDIM);   \
          else           wr_ = W0 + (size_t)o_*CDIM;                            \
          w1v = *(const float4*)(wr_ + k0_ + c4); }                             \
        if (LN) { lw = *(const float4*)(lnw + k0_ + c4);                        \
                  lb = *(const float4*)(lnb + k0_ + c4); } }

    GEMM_LOAD(0);

    #pragma unroll
    for (int kc = 0; kc < 8; ++kc) {
        if (kc) __syncthreads();
        if (MODE == 1) {   // combine split-KV partials for the chunk being stored
            const int h_ = kc >> 1;
            a0 = make_float4((p0[0].x+p0[1].x+p0[2].x+p0[3].x)*invl0[h_],
                             (p0[0].y+p0[1].y+p0[2].y+p0[3].y)*invl0[h_],
                             (p0[0].z+p0[1].z+p0[2].z+p0[3].z)*invl0[h_],
                             (p0[0].w+p0[1].w+p0[2].w+p0[3].w)*invl0[h_]);
            a1 = make_float4((p1[0].x+p1[1].x+p1[2].x+p1[3].x)*invl1[h_],
                             (p1[0].y+p1[1].y+p1[2].y+p1[3].y)*invl1[h_],
                             (p1[0].z+p1[1].z+p1[2].z+p1[3].z)*invl1[h_],
                             (p1[0].w+p1[1].w+p1[2].w+p1[3].w)*invl1[h_]);
        }
        if (LN) {
            a0.x = (a0.x - st0.x)*st0.y*lw.x + lb.x;
            a0.y = (a0.y - st0.x)*st0.y*lw.y + lb.y;
            a0.z = (a0.z - st0.x)*st0.y*lw.z + lb.z;
            a0.w = (a0.w - st0.x)*st0.y*lw.w + lb.w;
            a1.x = (a1.x - st1.x)*st1.y*lw.x + lb.x;
            a1.y = (a1.y - st1.x)*st1.y*lw.y + lb.y;
            a1.z = (a1.z - st1.x)*st1.y*lw.z + lb.z;
            a1.w = (a1.w - st1.x)*st1.y*lw.w + lb.w;
        }
        {
            float4 h0, h1;
            h0.x = tf32r(a0.x); h0.y = tf32r(a0.y); h0.z = tf32r(a0.z); h0.w = tf32r(a0.w);
            h1.x = tf32r(a1.x); h1.y = tf32r(a1.y); h1.z = tf32r(a1.z); h1.w = tf32r(a1.w);
            *(float4*)&Ah[lrow     ][c4] = h0;
            *(float4*)&Ah[lrow + 32][c4] = h1;
            if (EX) {
                float4 l0, l1;
                l0.x = tf32r(a0.x - h0.x); l0.y = tf32r(a0.y - h0.y);
                l0.z = tf32r(a0.z - h0.z); l0.w = tf32r(a0.w - h0.w);
                l1.x = tf32r(a1.x - h1.x); l1.y = tf32r(a1.y - h1.y);
                l1.z = tf32r(a1.z - h1.z); l1.w = tf32r(a1.w - h1.w);
                *(float4*)&Al[lrow     ][c4] = l0;
                *(float4*)&Al[lrow + 32][c4] = l1;
            }
            float4 hw0, hw1;
            hw0.x = tf32r(w0v.x); hw0.y = tf32r(w0v.y); hw0.z = tf32r(w0v.z); hw0.w = tf32r(w0v.w);
            hw1.x = tf32r(w1v.x); hw1.y = tf32r(w1v.y); hw1.z = tf32r(w1v.z); hw1.w = tf32r(w1v.w);
            *(float4*)&Wh[lrow     ][c4] = hw0;
            *(float4*)&Wh[lrow + 32][c4] = hw1;
            if (EX) {
                float4 l0, l1;
                l0.x = tf32r(w0v.x - hw0.x); l0.y = tf32r(w0v.y - hw0.y);
                l0.z = tf32r(w0v.z - hw0.z); l0.w = tf32r(w0v.w - hw0.w);
                l1.x = tf32r(w1v.x - hw1.x); l1.y = tf32r(w1v.y - hw1.y);
                l1.z = tf32r(w1v.z - hw1.z); l1.w = tf32r(w1v.w - hw1.w);
                *(float4*)&Wl[lrow     ][c4] = l0;
                *(float4*)&Wl[lrow + 32][c4] = l1;
            }
        }
        __syncthreads();
        if (kc < 7) GEMM_LOAD(kc + 1);

        #pragma unroll
        for (int ks = 0; ks < 2; ++ks) {
            const int k = ks * 8;
            const int mr = 16*warp;
            unsigned ah[4], al[4];
            ah[0] = __float_as_uint(Ah[mr + g    ][k + tg    ]);
            ah[1] = __float_as_uint(Ah[mr + g + 8][k + tg    ]);
            ah[2] = __float_as_uint(Ah[mr + g    ][k + tg + 4]);
            ah[3] = __float_as_uint(Ah[mr + g + 8][k + tg + 4]);
            if (EX) {
                al[0] = __float_as_uint(Al[mr + g    ][k + tg    ]);
                al[1] = __float_as_uint(Al[mr + g + 8][k + tg    ]);
                al[2] = __float_as_uint(Al[mr + g    ][k + tg + 4]);
                al[3] = __float_as_uint(Al[mr + g + 8][k + tg + 4]);
            }
            #pragma unroll
            for (int nt = 0; nt < 8; ++nt) {
                unsigned bh0 = __float_as_uint(Wh[8*nt + g][k + tg    ]);
                unsigned bh1 = __float_as_uint(Wh[8*nt + g][k + tg + 4]);
                mma_tf32(s[nt], ah[0], ah[1], ah[2], ah[3], bh0, bh1);
                if (EX) {
                    unsigned bl0 = __float_as_uint(Wl[8*nt + g][k + tg    ]);
                    unsigned bl1 = __float_as_uint(Wl[8*nt + g][k + tg + 4]);
                    mma_tf32(s[nt], ah[0], ah[1], ah[2], ah[3], bl0, bl1);
                    mma_tf32(s[nt], al[0], al[1], al[2], al[3], bh0, bh1);
                }
            }
        }
    }
#undef GEMM_LOAD

    // ---- epilogue ----
    const int mA = m0 + 16*warp + g;
    #pragma unroll
    for (int nt = 0; nt < 8; ++nt) {
        const int o = o0 + 8*nt + 2*tg;
        float2 v01 = make_float2(s[nt][0], s[nt][1]);
        float2 v23 = make_float2(s[nt][2], s[nt][3]);
        if (MODE == 0) {
            #pragma unroll
            for (int hf = 0; hf < 2; ++hf) {
                const int m = mA + 8*hf;
                float2 v = hf ? v23 : v01;
                const int b = m >> 12, n = m & 4095;
                if (o < 128) {
                    const int head = o >> 5, hd = o & 31;
                    *(unsigned*)&g_qh[((size_t)(b*HEADS + head)*NSEQ + n)*HD + hd] =
                        bf16x2(v.y*QSCALE, v.x*QSCALE);
                } else if (o < 256) {
                    const int oo = o - 128, head = oo >> 5, hd = oo & 31;
                    *(unsigned*)&g_kh[((size_t)(b*HEADS + head)*NSEQ + n)*HD + hd] =
                        bf16x2(v.y, v.x);
                } else {
                    const int oo = o - 256, head = oo >> 5, hd = oo & 31;
                    unsigned u = bf16x2(v.y, v.x);
                    size_t base = ((size_t)((b*HEADS + head)*128 + (n >> 5))*32 + hd)*32 + (n & 31);
                    g_vT[base]      = (u16)(u & 0xffffu);
                    g_vT[base + 32] = (u16)(u >> 16);
                }
            }
        } else if (MODE == 2) {
            float2 bv = *(const float2*)(bias + o);
            *(float2*)&g_c1[(size_t)mA*C2 + o] =
                make_float2(v01.x + bv.x, v01.y + bv.y);
            *(float2*)&g_c1[(size_t)(mA+8)*C2 + o] =
                make_float2(v23.x + bv.x, v23.y + bv.y);
        } else {
            const float* rs = (MODE == 1) ? resid_ext : g_xmid;
            float*       ds = (MODE == 1) ? g_xmid    : out_ext;
            float2 bv = *(const float2*)(bias + o);
            float2 r0 = *(const float2*)(rs + (size_t)mA*CDIM + o);
            float2 r1 = *(const float2*)(rs + (size_t)(mA+8)*CDIM + o);
            *(float2*)&ds[(size_t)mA*CDIM + o] =
                make_float2(v01.x + bv.x + r0.x, v01.y + bv.y + r0.y);
            *(float2*)&ds[(size_t)(mA+8)*CDIM + o] =
                make_float2(v23.x + bv.x + r1.x, v23.y + bv.y + r1.y);
        }
    }
}

// ---------------- Flash attention: bf16 m16n8k16, split-KV (R10 version) ----------------
__global__ void __launch_bounds__(128, 4) attn_kernel() {
    const int bh    = blockIdx.x;
    const int split = blockIdx.z;
    const int t     = threadIdx.x;
    const int warp  = t >> 5;
    const int lane  = t & 31;
    const int g     = lane >> 2;
    const int tg    = lane & 3;

    const int q0 = blockIdx.y*128 + warp*32;
    const u16* Qb  = g_qh + ((size_t)bh*NSEQ + q0)*HD;
    const u16* Kb  = g_kh + ((size_t)bh*NSEQ + (size_t)split*(NSEQ/SPLITS))*HD;
    const u16* Vtb = g_vT + ((size_t)(bh*128 + split*32))*1024;

    unsigned qf[2][2][4];
    #pragma unroll
    for (int mt = 0; mt < 2; ++mt)
        #pragma unroll
        for (int kk = 0; kk < 2; ++kk) {
            qf[mt][kk][0] = *(const unsigned*)&Qb[(16*mt + g    )*HD + 16*kk + 2*tg    ];
            qf[mt][kk][1] = *(const unsigned*)&Qb[(16*mt + g + 8)*HD + 16*kk + 2*tg    ];
            qf[mt][kk][2] = *(const unsigned*)&Qb[(16*mt + g    )*HD + 16*kk + 2*tg + 8];
            qf[mt][kk][3] = *(const unsigned*)&Qb[(16*mt + g + 8)*HD + 16*kk + 2*tg + 8];
        }

    __shared__ u16 Ks[2][32][KP];
    __shared__ u16 Vt[2][32][KP];

    float o[2][4][4] = {};
    float l[4] = {};

    const int lr  = t >> 2;
    const int lc8 = (t & 3) * 8;
    const float4* kptr = (const float4*)Kb  + t;
    const float4* vptr = (const float4*)Vtb + t;

    float4 ka = kptr[0];
    float4 va = vptr[0];

    for (int kt = 0; kt < TILES_PER_SPLIT; ++kt) {
        const int buf = kt & 1;
        *(float4*)&Ks[buf][lr][lc8] = ka;
        *(float4*)&Vt[buf][lr][lc8] = va;
        __syncthreads();

        if (kt + 1 < TILES_PER_SPLIT) {
            ka = kptr[(kt+1)*128];
            va = vptr[(kt+1)*128];
        }

        float s[2][4][4] = {};
        #pragma unroll
        for (int nt = 0; nt < 4; ++nt) {
            #pragma unroll
            for (int kk = 0; kk < 2; ++kk) {
                unsigned b0 = *(const unsigned*)&Ks[buf][8*nt + g][16*kk + 2*tg    ];
                unsigned b1 = *(const unsigned*)&Ks[buf][8*nt + g][16*kk + 2*tg + 8];
                mma_bf16(s[0][nt], qf[0][kk][0], qf[0][kk][1], qf[0][kk][2], qf[0][kk][3], b0, b1);
                mma_bf16(s[1][nt], qf[1][kk][0], qf[1][kk][1], qf[1][kk][2], qf[1][kk][3], b0, b1);
            }
        }

        unsigned pk[2][4][2];
        #pragma unroll
        for (int nt = 0; nt < 4; ++nt)
            #pragma unroll
            for (int mt = 0; mt < 2; ++mt) {
                float e0 = ex2(s[mt][nt][0]);
                float e1 = ex2(s[mt][nt][1]);
                float e2 = ex2(s[mt][nt][2]);
                float e3 = ex2(s[mt][nt][3]);
                l[2*mt]   += e0 + e1;
                l[2*mt+1] += e2 + e3;
                pk[mt][nt][0] = bf16x2(e1, e0);
                pk[mt][nt][1] = bf16x2(e3, e2);
            }

        #pragma unroll
        for (int kk2 = 0; kk2 < 2; ++kk2) {
            #pragma unroll
            for (int nd = 0; nd < 4; ++nd) {
                unsigned b0 = *(const unsigned*)&Vt[buf][8*nd + g][16*kk2 + 2*tg    ];
                unsigned b1 = *(const unsigned*)&Vt[buf][8*nd + g][16*kk2 + 2*tg + 8];
                #pragma unroll
                for (int mt = 0; mt < 2; ++mt)
                    mma_bf16(o[mt][nd],
                             pk[mt][2*kk2][0], pk[mt][2*kk2][1],
                             pk[mt][2*kk2+1][0], pk[mt][2*kk2+1][1],
                             b0, b1);
            }
        }
    }

    #pragma unroll
    for (int i = 0; i < 4; ++i) {
        l[i] += __shfl_xor_sync(0xffffffffu, l[i], 1);
        l[i] += __shfl_xor_sync(0xffffffffu, l[i], 2);
    }

    #pragma unroll
    for (int mt = 0; mt < 2; ++mt) {
        const size_t row = (size_t)bh*NSEQ + q0 + 16*mt + g;
        float* base0 = g_pacc + ((size_t)split*NROWS + row)*HD;
        float* base1 = base0 + 8*HD;
        #pragma unroll
        for (int nd = 0; nd < 4; ++nd) {
            *(float2*)(base0 + 8*nd + 2*tg) = make_float2(o[mt][nd][0], o[mt][nd][1]);
            *(float2*)(base1 + 8*nd + 2*tg) = make_float2(o[mt][nd][2], o[mt][nd][3]);
        }
        if (tg == 0) {
            g_pl[(size_t)split*NROWS + row    ] = l[2*mt];
            g_pl[(size_t)split*NROWS + row + 8] = l[2*mt+1];
        }
    }
}

// ---------------- dw 3x3 + 5x5 + gate: spatially tiled, smem halo ----------------
// grid (64 tiles, 4 ch-groups, 2 batch); block (32 ch-pairs, 8 rows).
__global__ void __launch_bounds__(256) dw_gate_kernel(const float* __restrict__ w33,
                                                      const float* __restrict__ b33,
                                                      const float* __restrict__ w55,
                                                      const float* __restrict__ b55) {
    __shared__ float sIn[144][64];   // 12x12 halo x (32 a-ch + 32 g-ch)
    __shared__ float sw3[64][9];
    __shared__ float sw5[64][25];
    __shared__ float sbb[64];

    const int c   = threadIdx.x;
    const int py  = threadIdx.y;
    const int tid = py*32 + c;
    const int ca0 = blockIdx.y * 32;
    const int bz  = blockIdx.z;
    const int ty0 = (blockIdx.x >> 3) * 8;
    const int tx0 = (blockIdx.x & 7) * 8;

    for (int i = tid; i < 64*9; i += 256) {
        int s = i / 9, k = i - s*9;
        int gc = (s < 32) ? (ca0 + s) : (128 + ca0 + s - 32);
        sw3[s][k] = w33[gc*9 + k];
    }
    for (int i = tid; i < 64*25; i += 256) {
        int s = i / 25, k = i - s*25;
        int gc = (s < 32) ? (ca0 + s) : (128 + ca0 + s - 32);
        sw5[s][k] = w55[gc*25 + k];
    }
    if (tid < 64) {
        int gc = (tid < 32) ? (ca0 + tid) : (128 + ca0 + tid - 32);
        sbb[tid] = b33[gc] + b55[gc];
    }

    const float* cbase = g_c1 + (size_t)bz*NSEQ*C2;
    for (int i = tid; i < 2304; i += 256) {       // 144 px x 16 float4
        int px = i >> 4, c4 = i & 15;
        int hy = ty0 + (px/12) - 2, hx = tx0 + (px - (px/12)*12) - 2;
        float4 v = make_float4(0.f, 0.f, 0.f, 0.f);
        if (hy >= 0 && hy < 64 && hx >= 0 && hx < 64) {
            int gc = (c4 < 8) ? (ca0 + c4*4) : (128 + ca0 + (c4-8)*4);
            v = *(const float4*)(cbase + (size_t)(hy*64 + hx)*C2 + gc);
        }
        *(float4*)&sIn[px][c4*4] = v;
    }
    __syncthreads();

    // cache weights in registers
    float w5a[25], w5g[25];
    #pragma unroll
    for (int k = 0; k < 25; ++k) { w5a[k] = sw5[c][k]; w5g[k] = sw5[32+c][k]; }
    float w3a[9], w3g[9];
    #pragma unroll
    for (int k = 0; k < 9; ++k)  { w3a[k] = sw3[c][k]; w3g[k] = sw3[32+c][k]; }
    const float ba = sbb[c], bg = sbb[32+c];

    float* gout = g_gate + ((size_t)bz*NSEQ + (ty0+py)*64 + tx0)*CDIM + ca0 + c;

    #pragma unroll
    for (int x = 0; x < 8; ++x) {
        const int p0 = (py+2)*12 + (x+2);
        float a = ba + sIn[p0][c];
        float g = bg + sIn[p0][32+c];
        #pragma unroll
        for (int dy = -2; dy <= 2; ++dy) {
            #pragma unroll
            for (int dx = -2; dx <= 2; ++dx) {
                const int pp = p0 + dy*12 + dx;
                const float va = sIn[pp][c];
                const float vg = sIn[pp][32+c];
                const int i5 = (dy+2)*5 + (dx+2);
                a = fmaf(va, w5a[i5], a);
                g = fmaf(vg, w5g[i5], g);
                if (dy >= -1 && dy <= 1 && dx >= -1 && dx <= 1) {
                    const int i3 = (dy+1)*3 + (dx+1);
                    a = fmaf(va, w3a[i3], a);
                    g = fmaf(vg, w3g[i3], g);
                }
            }
        }
        gout[x*CDIM] = a * g;
    }
}

// ---------------- launch ----------------
extern "C" void kernel_launch(void* const* d_in, const int* in_sizes, int n_in,
                              void* d_out, int out_size) {
    (void)in_sizes; (void)n_in; (void)out_size;
    const float* x       = (const float*)d_in[0];
    const float* ln1_w   = (const float*)d_in[3];
    const float* ln1_b   = (const float*)d_in[4];
    const float* q_w     = (const float*)d_in[5];
    const float* kv_w    = (const float*)d_in[6];
    const float* proj_w  = (const float*)d_in[7];
    const float* proj_b  = (const float*)d_in[8];
    const float* ln2_w   = (const float*)d_in[9];
    const float* ln2_b   = (const float*)d_in[10];
    const float* conv1_w = (const float*)d_in[11];
    const float* conv1_b = (const float*)d_in[12];
    const float* conv33_w= (const float*)d_in[13];
    const float* conv33_b= (const float*)d_in[14];
    const float* conv55_w= (const float*)d_in[15];
    const float* conv55_b= (const float*)d_in[16];
    const float* conv4_w = (const float*)d_in[17];
    const float* conv4_b = (const float*)d_in[18];
    float* out = (float*)d_out;

    ln_stats<1><<<MTOT/8, 256>>>(x);                                             // 0
    gemm_mma<0><<<dim3(128, 6), 128>>>(x, q_w, kv_w, nullptr,
                                       ln1_w, ln1_b, nullptr, nullptr);          // 1
    attn_kernel<<<dim3(8, 32, 4), 128>>>();                                      // 2
    gemm_mma<1><<<dim3(128, 2), 128>>>(nullptr, proj_w, nullptr, proj_b,
                                       nullptr, nullptr, x, nullptr);            // 3 (profiled)
    ln_stats<2><<<MTOT/8, 256>>>(nullptr);                                       // 4
    gemm_mma<2><<<dim3(128, 4), 128>>>(nullptr, conv1_w, nullptr, conv1_b,
                                       ln2_w, ln2_b, nullptr, nullptr);          // 5
    dw_gate_kernel<<<dim3(64, 4, 2), dim3(32, 8)>>>(conv33_w, conv33_b,
                                                    conv55_w, conv55_b);         // 6
    gemm_mma<3><<<dim3(128, 2), 128>>>(nullptr, conv4_w, nullptr, conv4_b,
                                       nullptr, nullptr, nullptr, out);          // 7
}